// round 2
// baseline (speedup 1.0000x reference)
#include <cuda_runtime.h>
#include <math.h>

#define NUM_USERS 60000
#define NUM_ITEMS 40000
#define NUM_NODES 100000
#define EMB 64
#define HID 32
#define N_EDGES 1600000
#define BATCH 16384

// Scratch (allocation-free rule: device globals)
__device__ __align__(16) float g_h1[NUM_NODES * HID];     // lin1 output (pre-agg)
__device__ __align__(16) float g_agg1[NUM_NODES * HID];   // segment-sum layer 1
__device__ __align__(16) float g_h2lin[NUM_NODES * EMB];  // lin2 output (pre-agg)

// ---------------------------------------------------------------------------
// K1: h1[n][j] = sum_k feat[n][k] * gc1_w[j][k] + gc1_b[j]
// warp per node, lane = output j
__global__ void lin1_kernel(const float* __restrict__ uemb,
                            const float* __restrict__ iemb,
                            const float* __restrict__ W,
                            const float* __restrict__ b) {
    __shared__ float sW[HID][EMB + 1];  // pad to kill bank conflicts
    int tid = threadIdx.x;
    for (int i = tid; i < HID * EMB; i += blockDim.x)
        sW[i / EMB][i % EMB] = W[i];
    __syncthreads();

    int lane = tid & 31;
    int node = blockIdx.x * (blockDim.x >> 5) + (tid >> 5);
    if (node >= NUM_NODES) return;

    const float4* feat = (node < NUM_USERS)
        ? (const float4*)(uemb + (size_t)node * EMB)
        : (const float4*)(iemb + (size_t)(node - NUM_USERS) * EMB);

    float acc = b[lane];
#pragma unroll
    for (int k4 = 0; k4 < EMB / 4; k4++) {
        float4 x = __ldg(&feat[k4]);
        acc += x.x * sW[lane][k4 * 4 + 0];
        acc += x.y * sW[lane][k4 * 4 + 1];
        acc += x.z * sW[lane][k4 * 4 + 2];
        acc += x.w * sW[lane][k4 * 4 + 3];
    }
    g_h1[(size_t)node * HID + lane] = acc;
}

// ---------------------------------------------------------------------------
// zero n floats (n % 4 == 0), float4 stores
__global__ void zero_kernel(float4* __restrict__ p, int n4) {
    int i = blockIdx.x * blockDim.x + threadIdx.x;
    if (i < n4) p[i] = make_float4(0.f, 0.f, 0.f, 0.f);
}

// ---------------------------------------------------------------------------
// K3: edge scatter, layer 1 (HID=32 feats). 8 threads per edge (float4 each)
__global__ void scatter1_kernel(const int* __restrict__ rows,
                                const int* __restrict__ cols,
                                const float* __restrict__ vals) {
    int idx = blockIdx.x * blockDim.x + threadIdx.x;
    int e = idx >> 3;
    int f4 = idx & 7;
    if (e >= N_EDGES) return;
    int r = __ldg(&rows[e]);
    int c = __ldg(&cols[e]);
    float v = __ldg(&vals[e]);
    float4 h = ((const float4*)g_h1)[(size_t)c * (HID / 4) + f4];
    float* dst = g_agg1 + (size_t)r * HID + f4 * 4;
    atomicAdd(dst + 0, v * h.x);
    atomicAdd(dst + 1, v * h.y);
    atomicAdd(dst + 2, v * h.z);
    atomicAdd(dst + 3, v * h.w);
}

// ---------------------------------------------------------------------------
// K4: h2lin[n][j] = sum_k relu(agg1[n][k]) * gc2_w[j][k] + gc2_b[j]
// warp per node; lane handles j = lane and j = lane+32
__global__ void lin2_kernel(const float* __restrict__ W2,
                            const float* __restrict__ b2) {
    __shared__ float sW[EMB][HID + 1];
    int tid = threadIdx.x;
    for (int i = tid; i < EMB * HID; i += blockDim.x)
        sW[i / HID][i % HID] = W2[i];
    __syncthreads();

    int lane = tid & 31;
    int node = blockIdx.x * (blockDim.x >> 5) + (tid >> 5);
    if (node >= NUM_NODES) return;

    const float4* hin = (const float4*)(g_agg1 + (size_t)node * HID);
    float acc0 = b2[lane];
    float acc1 = b2[lane + 32];
#pragma unroll
    for (int k4 = 0; k4 < HID / 4; k4++) {
        float4 x = hin[k4];
        x.x = fmaxf(x.x, 0.f);
        x.y = fmaxf(x.y, 0.f);
        x.z = fmaxf(x.z, 0.f);
        x.w = fmaxf(x.w, 0.f);
        acc0 += x.x * sW[lane][k4 * 4 + 0] + x.y * sW[lane][k4 * 4 + 1]
              + x.z * sW[lane][k4 * 4 + 2] + x.w * sW[lane][k4 * 4 + 3];
        acc1 += x.x * sW[lane + 32][k4 * 4 + 0] + x.y * sW[lane + 32][k4 * 4 + 1]
              + x.z * sW[lane + 32][k4 * 4 + 2] + x.w * sW[lane + 32][k4 * 4 + 3];
    }
    g_h2lin[(size_t)node * EMB + lane] = acc0;
    g_h2lin[(size_t)node * EMB + lane + 32] = acc1;
}

// ---------------------------------------------------------------------------
// K6: edge scatter, layer 2 (EMB=64 feats). 16 threads per edge (float4 each)
__global__ void scatter2_kernel(const int* __restrict__ rows,
                                const int* __restrict__ cols,
                                const float* __restrict__ vals,
                                float* __restrict__ out_h2) {
    int idx = blockIdx.x * blockDim.x + threadIdx.x;
    int e = idx >> 4;
    int f4 = idx & 15;
    if (e >= N_EDGES) return;
    int r = __ldg(&rows[e]);
    int c = __ldg(&cols[e]);
    float v = __ldg(&vals[e]);
    float4 h = ((const float4*)g_h2lin)[(size_t)c * (EMB / 4) + f4];
    float* dst = out_h2 + (size_t)r * EMB + f4 * 4;
    atomicAdd(dst + 0, v * h.x);
    atomicAdd(dst + 1, v * h.y);
    atomicAdd(dst + 2, v * h.z);
    atomicAdd(dst + 3, v * h.w);
}

// ---------------------------------------------------------------------------
// K7: relu in place (float4)
__global__ void relu_kernel(float4* __restrict__ p, int n4) {
    int i = blockIdx.x * blockDim.x + threadIdx.x;
    if (i < n4) {
        float4 x = p[i];
        x.x = fmaxf(x.x, 0.f);
        x.y = fmaxf(x.y, 0.f);
        x.z = fmaxf(x.z, 0.f);
        x.w = fmaxf(x.w, 0.f);
        p[i] = x;
    }
}

// ---------------------------------------------------------------------------
// K8: prediction MLP. warp per batch sample; lane = hidden unit j (32)
__global__ void predict_kernel(const int* __restrict__ uid,
                               const int* __restrict__ iid,
                               const float* __restrict__ h2,
                               const float* __restrict__ p1w,
                               const float* __restrict__ p1b,
                               const float* __restrict__ p2w,
                               const float* __restrict__ p2b,
                               float* __restrict__ scores) {
    __shared__ float sP1[HID][2 * EMB + 1];  // 32 x 129
    __shared__ float sP2[HID];
    int tid = threadIdx.x;
    for (int i = tid; i < HID * 2 * EMB; i += blockDim.x)
        sP1[i / (2 * EMB)][i % (2 * EMB)] = p1w[i];
    if (tid < HID) sP2[tid] = p2w[tid];
    __syncthreads();

    int lane = tid & 31;
    int s = blockIdx.x * (blockDim.x >> 5) + (tid >> 5);
    if (s >= BATCH) return;

    int u = __ldg(&uid[s]);
    int it = __ldg(&iid[s]);
    const float4* bu = (const float4*)(h2 + (size_t)u * EMB);
    const float4* bi = (const float4*)(h2 + (size_t)(NUM_USERS + it) * EMB);

    float acc = p1b[lane];
#pragma unroll
    for (int k4 = 0; k4 < EMB / 4; k4++) {
        float4 x = __ldg(&bu[k4]);
        acc += x.x * sP1[lane][k4 * 4 + 0] + x.y * sP1[lane][k4 * 4 + 1]
             + x.z * sP1[lane][k4 * 4 + 2] + x.w * sP1[lane][k4 * 4 + 3];
    }
#pragma unroll
    for (int k4 = 0; k4 < EMB / 4; k4++) {
        float4 x = __ldg(&bi[k4]);
        acc += x.x * sP1[lane][EMB + k4 * 4 + 0] + x.y * sP1[lane][EMB + k4 * 4 + 1]
             + x.z * sP1[lane][EMB + k4 * 4 + 2] + x.w * sP1[lane][EMB + k4 * 4 + 3];
    }
    float z = fmaxf(acc, 0.f);
    float ssum = z * sP2[lane];
#pragma unroll
    for (int o = 16; o > 0; o >>= 1)
        ssum += __shfl_xor_sync(0xffffffffu, ssum, o);
    if (lane == 0)
        scores[s] = 1.f / (1.f + expf(-(ssum + p2b[0])));
}

// ---------------------------------------------------------------------------
extern "C" void kernel_launch(void* const* d_in, const int* in_sizes, int n_in,
                              void* d_out, int out_size) {
    const int*   user_ids = (const int*)d_in[0];
    const int*   item_ids = (const int*)d_in[1];
    const int*   adj_rows = (const int*)d_in[2];
    const int*   adj_cols = (const int*)d_in[3];
    const float* adj_vals = (const float*)d_in[4];
    const float* uemb     = (const float*)d_in[5];
    const float* iemb     = (const float*)d_in[6];
    const float* gc1w     = (const float*)d_in[7];
    const float* gc1b     = (const float*)d_in[8];
    const float* gc2w     = (const float*)d_in[9];
    const float* gc2b     = (const float*)d_in[10];
    const float* p1w      = (const float*)d_in[11];
    const float* p1b      = (const float*)d_in[12];
    const float* p2w      = (const float*)d_in[13];
    const float* p2b      = (const float*)d_in[14];

    float* out = (float*)d_out;
    float* out_h2 = out + BATCH;  // [NUM_NODES * EMB] = concat(user_emb, item_emb)

    float* d_agg1;
    cudaGetSymbolAddress((void**)&d_agg1, g_agg1);

    const int TB = 256;

    // L1 linear
    lin1_kernel<<<NUM_NODES / 8, TB>>>(uemb, iemb, gc1w, gc1b);
    // zero agg1
    zero_kernel<<<(NUM_NODES * HID / 4) / TB, TB>>>((float4*)d_agg1, NUM_NODES * HID / 4);
    // edge scatter L1: 8 threads/edge
    scatter1_kernel<<<(N_EDGES * 8) / TB, TB>>>(adj_rows, adj_cols, adj_vals);
    // L2 linear (fused relu on input)
    lin2_kernel<<<NUM_NODES / 8, TB>>>(gc2w, gc2b);
    // zero output h2 region
    zero_kernel<<<(NUM_NODES * EMB / 4) / TB, TB>>>((float4*)out_h2, NUM_NODES * EMB / 4);
    // edge scatter L2: 16 threads/edge
    scatter2_kernel<<<(N_EDGES * 16) / TB, TB>>>(adj_rows, adj_cols, adj_vals, out_h2);
    // relu in place on output embeddings
    relu_kernel<<<(NUM_NODES * EMB / 4) / TB, TB>>>((float4*)out_h2, NUM_NODES * EMB / 4);
    // prediction head
    predict_kernel<<<BATCH / 8, TB>>>(user_ids, item_ids, out_h2,
                                      p1w, p1b, p2w, p2b, out);
}